// round 1
// baseline (speedup 1.0000x reference)
#include <cuda_runtime.h>
#include <cuda_bf16.h>
#include <math.h>

#define B_SZ    2
#define L_SEQ   2048
#define D_MODEL 768
#define D_INNER 1536
#define E2      3072          // 2 * D_INNER
#define D_STATE 16
#define DT_RANK 48
#define KDBL    80            // DT_RANK + 2*D_STATE
#define D_CONV  4

// ---------------- scratch (device globals; no allocation) ----------------
__device__ float g_xz  [B_SZ * E2 * L_SEQ];            // [b][e][l]
__device__ float g_xc  [2][B_SZ * D_INNER * L_SEQ];    // conv+silu output per branch (scan-time domain)
__device__ float g_xdbl[2][B_SZ * KDBL * L_SEQ];       // [b][k80][t]
__device__ float g_dt  [2][B_SZ * D_INNER * L_SEQ];    // softplus(dt)
__device__ float g_bc  [2][B_SZ * L_SEQ * 32];         // [b][t][0:16]=B, [16:32]=C
__device__ float g_y   [2][B_SZ * D_INNER * L_SEQ];    // scan output (incl. D*x)
__device__ float g_out [B_SZ * D_INNER * L_SEQ];       // combined, pre-output-GEMM

// ---------------- generic 64x64x16 fp32 GEMM ----------------
// C[i][j] = sum_k A[i][k] * B[k][j]
// A row-major [M][K], lda.
// BT=false: B stored [K][N] (ldb = row stride). BT=true: B stored [N][K] (B[k][j] = Bm[j*ldb+k]).
// ST=false: C[i*ldc+j].  ST=true: C[j*ldc+i] (store transposed, staged through smem; needs M,N %64==0).
template<bool BT, bool ST>
__global__ void gemm64(const float* __restrict__ A, const float* __restrict__ Bm,
                       float* __restrict__ C, int M, int N, int K,
                       int lda, int ldb, int ldc,
                       long sAz, long sBz, long sCz)
{
    A  += (size_t)blockIdx.z * sAz;
    Bm += (size_t)blockIdx.z * sBz;
    C  += (size_t)blockIdx.z * sCz;

    __shared__ float As[16][68];
    __shared__ float Bs[16][64];
    __shared__ float Cs[64][65];

    int tid = threadIdx.x;             // 256 threads
    int tx = tid & 15, ty = tid >> 4;  // 16 x 16
    int row0 = blockIdx.y * 64, col0 = blockIdx.x * 64;

    float acc[4][4] = {};

    for (int k0 = 0; k0 < K; k0 += 16) {
        // --- load A tile (64 x 16) ---
        {
            int m = tid >> 2, k4 = (tid & 3) * 4;
            float4 v = make_float4(0.f, 0.f, 0.f, 0.f);
            if (row0 + m < M)
                v = *(const float4*)(A + (size_t)(row0 + m) * lda + k0 + k4);
            As[k4 + 0][m] = v.x; As[k4 + 1][m] = v.y;
            As[k4 + 2][m] = v.z; As[k4 + 3][m] = v.w;
        }
        // --- load B tile (16 x 64) ---
        if (BT) {
            int j = tid >> 2, k4 = (tid & 3) * 4;
            float4 v = *(const float4*)(Bm + (size_t)(col0 + j) * ldb + k0 + k4);
            Bs[k4 + 0][j] = v.x; Bs[k4 + 1][j] = v.y;
            Bs[k4 + 2][j] = v.z; Bs[k4 + 3][j] = v.w;
        } else {
            int k = tid >> 4, n4 = (tid & 15) * 4;
            *(float4*)&Bs[k][n4] = *(const float4*)(Bm + (size_t)(k0 + k) * ldb + col0 + n4);
        }
        __syncthreads();

        #pragma unroll
        for (int k = 0; k < 16; k++) {
            float4 av = *(const float4*)&As[k][ty * 4];
            float4 bv = *(const float4*)&Bs[k][tx * 4];
            float aa[4] = {av.x, av.y, av.z, av.w};
            float bb[4] = {bv.x, bv.y, bv.z, bv.w};
            #pragma unroll
            for (int i = 0; i < 4; i++)
                #pragma unroll
                for (int j = 0; j < 4; j++)
                    acc[i][j] = fmaf(aa[i], bb[j], acc[i][j]);
        }
        __syncthreads();
    }

    if (!ST) {
        #pragma unroll
        for (int i = 0; i < 4; i++) {
            int r = row0 + ty * 4 + i;
            if (r < M) {
                float4 v = make_float4(acc[i][0], acc[i][1], acc[i][2], acc[i][3]);
                *(float4*)(C + (size_t)r * ldc + col0 + tx * 4) = v;
            }
        }
    } else {
        #pragma unroll
        for (int i = 0; i < 4; i++)
            #pragma unroll
            for (int j = 0; j < 4; j++)
                Cs[tx * 4 + j][ty * 4 + i] = acc[i][j];
        __syncthreads();
        int jr = tid >> 4;          // 0..15
        int i4 = (tid & 15) * 4;
        #pragma unroll
        for (int rep = 0; rep < 4; rep++) {
            int j = jr + rep * 16;
            float4 v = make_float4(Cs[j][i4], Cs[j][i4 + 1], Cs[j][i4 + 2], Cs[j][i4 + 3]);
            *(float4*)(C + (size_t)(col0 + j) * ldc + row0 + i4) = v;
        }
    }
}

// ---------------- causal depthwise conv + SiLU ----------------
// rev=0: y[t] = sum_k w[k] * x[t-3+k]
// rev=1: operates on reversed sequence s[t] = x[L-1-t]; output indexed by scan-time t.
__global__ void conv_silu_kernel(const float* __restrict__ xz, const float* __restrict__ w,
                                 const float* __restrict__ bias, float* __restrict__ out, int rev)
{
    int t = blockIdx.x * blockDim.x + threadIdx.x;
    int d = blockIdx.y;
    int b = blockIdx.z;
    const float* xp = xz + ((size_t)b * E2 + d) * L_SEQ;
    float acc = bias[d];
    #pragma unroll
    for (int k = 0; k < 4; k++) {
        int s = t - 3 + k;
        float xv = 0.f;
        if (s >= 0) {
            int pos = rev ? (L_SEQ - 1 - s) : s;
            xv = xp[pos];
        }
        acc = fmaf(w[d * 4 + k], xv, acc);
    }
    float sv = acc / (1.f + __expf(-acc));
    out[((size_t)b * D_INNER + d) * L_SEQ + t] = sv;
}

// ---------------- dt = softplus(W_dt @ dt_lo + b_dt) ----------------
__global__ void dt_kernel(const float* __restrict__ xdbl, const float* __restrict__ Wdt,
                          const float* __restrict__ bdt, float* __restrict__ out)
{
    int l = blockIdx.x * blockDim.x + threadIdx.x;
    int d = blockIdx.y, b = blockIdx.z;
    const float* xp = xdbl + (size_t)b * KDBL * L_SEQ + l;
    float acc = bdt[d];
    #pragma unroll
    for (int r = 0; r < DT_RANK; r++)
        acc = fmaf(Wdt[d * DT_RANK + r], xp[(size_t)r * L_SEQ], acc);
    float sp = (acc > 20.f) ? acc : log1pf(__expf(acc));
    out[((size_t)b * D_INNER + d) * L_SEQ + l] = sp;
}

// ---------------- transpose B,C rows of x_dbl into [b][t][32] ----------------
__global__ void bc_kernel(const float* __restrict__ xdbl, float* __restrict__ bc)
{
    int idx = blockIdx.x * blockDim.x + threadIdx.x;   // over B_SZ*L_SEQ*32
    if (idx >= B_SZ * L_SEQ * 32) return;
    int i = idx & 31;
    int t = (idx >> 5) & (L_SEQ - 1);
    int b = idx >> 16;                                  // L_SEQ*32 == 65536
    bc[idx] = xdbl[(size_t)b * KDBL * L_SEQ + (size_t)(DT_RANK + i) * L_SEQ + t];
}

// ---------------- selective scan ----------------
// half-warp (16 lanes = 16 states) per (b,d) row; 256 threads = 16 rows / block
__global__ void scan_kernel(const float* __restrict__ xc, const float* __restrict__ dt,
                            const float* __restrict__ bc, const float* __restrict__ A_log,
                            const float* __restrict__ Dp, float* __restrict__ y)
{
    int half = threadIdx.x >> 4;
    int n    = threadIdx.x & 15;
    int row  = blockIdx.x * 16 + half;          // in [0, B_SZ*D_INNER)
    int b = row / D_INNER, d = row % D_INNER;

    float a  = -__expf(A_log[d * D_STATE + n]);
    float Dv = Dp[d];
    const float* dtp = dt + (size_t)row * L_SEQ;
    const float* xp  = xc + (size_t)row * L_SEQ;
    const float* bcp = bc + (size_t)b * L_SEQ * 32;
    float* yp = y + (size_t)row * L_SEQ;

    float h = 0.f;
    #pragma unroll 2
    for (int t = 0; t < L_SEQ; t++) {
        float dtv = __ldg(dtp + t);
        float xv  = __ldg(xp + t);
        float bv  = __ldg(bcp + t * 32 + n);
        float cv  = __ldg(bcp + t * 32 + 16 + n);
        float dA  = __expf(dtv * a);
        h = fmaf(dA, h, dtv * xv * bv);
        float p = h * cv;
        p += __shfl_xor_sync(0xffffffffu, p, 1);
        p += __shfl_xor_sync(0xffffffffu, p, 2);
        p += __shfl_xor_sync(0xffffffffu, p, 4);
        p += __shfl_xor_sync(0xffffffffu, p, 8);
        if (n == 0) yp[t] = fmaf(Dv, xv, p);
    }
}

// ---------------- combine: 0.5 * silu(z) * (y_f + rev(y_b)) ----------------
__global__ void combine_kernel(const float* __restrict__ xz, const float* __restrict__ yf,
                               const float* __restrict__ yb, float* __restrict__ out)
{
    int idx = blockIdx.x * blockDim.x + threadIdx.x;  // over B_SZ*D_INNER*L_SEQ
    int pos = idx & (L_SEQ - 1);
    int bd  = idx >> 11;                               // L_SEQ = 2048
    int b = bd / D_INNER, d = bd % D_INNER;
    float z  = xz[((size_t)b * E2 + D_INNER + d) * L_SEQ + pos];
    float sz = z / (1.f + __expf(-z));
    float v  = 0.5f * sz * (yf[idx] + yb[(size_t)bd * L_SEQ + (L_SEQ - 1 - pos)]);
    out[idx] = v;
}

// ---------------- host launcher ----------------
extern "C" void kernel_launch(void* const* d_in, const int* in_sizes, int n_in,
                              void* d_out, int out_size)
{
    (void)in_sizes; (void)n_in; (void)out_size;
    const float* hidden   = (const float*)d_in[0];
    const float* W_in     = (const float*)d_in[1];
    const float* conv_w   = (const float*)d_in[2];
    const float* conv_b   = (const float*)d_in[3];
    const float* conv_w_b = (const float*)d_in[4];
    const float* conv_b_b = (const float*)d_in[5];
    const float* W_x      = (const float*)d_in[6];
    const float* W_x_b    = (const float*)d_in[7];
    const float* W_dt     = (const float*)d_in[8];
    const float* b_dt     = (const float*)d_in[9];
    const float* W_dt_b   = (const float*)d_in[10];
    const float* b_dt_b   = (const float*)d_in[11];
    const float* A_log    = (const float*)d_in[12];
    const float* A_b_log  = (const float*)d_in[13];
    const float* Dp       = (const float*)d_in[14];
    const float* Dp_b     = (const float*)d_in[15];
    const float* W_out    = (const float*)d_in[16];

    float *xz, *xcb, *xdb, *dtb, *bcb, *yb_, *outb;
    cudaGetSymbolAddress((void**)&xz,   g_xz);
    cudaGetSymbolAddress((void**)&xcb,  g_xc);
    cudaGetSymbolAddress((void**)&xdb,  g_xdbl);
    cudaGetSymbolAddress((void**)&dtb,  g_dt);
    cudaGetSymbolAddress((void**)&bcb,  g_bc);
    cudaGetSymbolAddress((void**)&yb_,  g_y);
    cudaGetSymbolAddress((void**)&outb, g_out);

    const size_t S_XC = (size_t)B_SZ * D_INNER * L_SEQ;
    const size_t S_XD = (size_t)B_SZ * KDBL * L_SEQ;
    const size_t S_BC = (size_t)B_SZ * L_SEQ * 32;
    float* xc0 = xcb;            float* xc1 = xcb + S_XC;
    float* xd0 = xdb;            float* xd1 = xdb + S_XD;
    float* dt0 = dtb;            float* dt1 = dtb + S_XC;
    float* bc0 = bcb;            float* bc1 = bcb + S_BC;
    float* y0  = yb_;            float* y1  = yb_ + S_XC;

    dim3 blk(256);

    // 1) xz[b][e][l] = sum_d hidden[b][l][d] * W_in[e][d]
    gemm64<true, false><<<dim3(L_SEQ / 64, E2 / 64, B_SZ), blk>>>(
        W_in, hidden, xz, E2, L_SEQ, D_MODEL,
        D_MODEL, D_MODEL, L_SEQ,
        0L, (long)L_SEQ * D_MODEL, (long)E2 * L_SEQ);

    // 2) depthwise conv + silu (fwd and reversed)
    conv_silu_kernel<<<dim3(L_SEQ / 256, D_INNER, B_SZ), blk>>>(xz, conv_w,   conv_b,   xc0, 0);
    conv_silu_kernel<<<dim3(L_SEQ / 256, D_INNER, B_SZ), blk>>>(xz, conv_w_b, conv_b_b, xc1, 1);

    // 3) x_dbl = W_x @ x~   (M=80 -> 2 row tiles with guards)
    gemm64<false, false><<<dim3(L_SEQ / 64, 2, B_SZ), blk>>>(
        W_x, xc0, xd0, KDBL, L_SEQ, D_INNER,
        D_INNER, L_SEQ, L_SEQ,
        0L, (long)D_INNER * L_SEQ, (long)KDBL * L_SEQ);
    gemm64<false, false><<<dim3(L_SEQ / 64, 2, B_SZ), blk>>>(
        W_x_b, xc1, xd1, KDBL, L_SEQ, D_INNER,
        D_INNER, L_SEQ, L_SEQ,
        0L, (long)D_INNER * L_SEQ, (long)KDBL * L_SEQ);

    // 4) dt
    dt_kernel<<<dim3(L_SEQ / 256, D_INNER, B_SZ), blk>>>(xd0, W_dt,   b_dt,   dt0);
    dt_kernel<<<dim3(L_SEQ / 256, D_INNER, B_SZ), blk>>>(xd1, W_dt_b, b_dt_b, dt1);

    // 5) B/C transpose
    bc_kernel<<<(B_SZ * L_SEQ * 32) / 256, blk>>>(xd0, bc0);
    bc_kernel<<<(B_SZ * L_SEQ * 32) / 256, blk>>>(xd1, bc1);

    // 6) selective scan
    scan_kernel<<<B_SZ * D_INNER / 16, blk>>>(xc0, dt0, bc0, A_log,   Dp,   y0);
    scan_kernel<<<B_SZ * D_INNER / 16, blk>>>(xc1, dt1, bc1, A_b_log, Dp_b, y1);

    // 7) combine branches with silu(z)
    combine_kernel<<<(B_SZ * D_INNER * L_SEQ) / 256, blk>>>(xz, y0, y1, outb);

    // 8) final projection: out[b][l][m] = sum_d out[b][d][l] * W_out[m][d]
    gemm64<false, true><<<dim3(L_SEQ / 64, D_MODEL / 64, B_SZ), blk>>>(
        W_out, outb, (float*)d_out, D_MODEL, L_SEQ, D_INNER,
        D_INNER, L_SEQ, D_MODEL,
        0L, (long)D_INNER * L_SEQ, (long)L_SEQ * D_MODEL);
}

// round 8
// speedup vs baseline: 1.9506x; 1.9506x over previous
#include <cuda_runtime.h>
#include <cuda_bf16.h>
#include <math.h>
#include <stdint.h>

#define B_SZ    2
#define L_SEQ   2048
#define D_MODEL 768
#define D_INNER 1536
#define E2      3072
#define D_STATE 16
#define DT_RANK 48
#define KDBL    80
#define D_CONV  4

// ---------------- scratch (device globals) ----------------
__device__ float g_xz  [B_SZ * E2 * L_SEQ];
__device__ float g_xc  [2][B_SZ * D_INNER * L_SEQ];
__device__ float g_xdbl[2][B_SZ * KDBL * L_SEQ];
__device__ float g_dt  [2][B_SZ * D_INNER * L_SEQ];
__device__ float g_bc  [2][B_SZ * L_SEQ * 32];
__device__ float g_y   [2][B_SZ * D_INNER * L_SEQ];

// bf16 hi/lo split buffers
__device__ __nv_bfloat16 g_winh[E2 * D_MODEL],      g_winl[E2 * D_MODEL];
__device__ __nv_bfloat16 g_hidh[B_SZ * L_SEQ * D_MODEL], g_hidl[B_SZ * L_SEQ * D_MODEL];
__device__ __nv_bfloat16 g_wouth[D_MODEL * D_INNER], g_woutl[D_MODEL * D_INNER];
__device__ __nv_bfloat16 g_chi[B_SZ * L_SEQ * D_INNER], g_clo[B_SZ * L_SEQ * D_INNER];

// ================= helpers (base-target sm_103 safe) =================
__device__ __forceinline__ uint32_t smem_u32(const void* p) {
    uint32_t a;
    asm("{ .reg .u64 t; cvta.to.shared.u64 t, %1; cvt.u32.u64 %0, t; }" : "=r"(a) : "l"(p));
    return a;
}
__device__ __forceinline__ void cp16(uint32_t s, const void* g) {
    asm volatile("cp.async.cg.shared.global [%0], [%1], 16;" :: "r"(s), "l"(g));
}
#define CP_COMMIT() asm volatile("cp.async.commit_group;" ::: "memory")
#define CP_WAIT(N)  asm volatile("cp.async.wait_group %0;" :: "n"(N) : "memory")

#define LDMX4(r, addr) \
    asm volatile("ldmatrix.sync.aligned.m8n8.x4.shared.b16 {%0,%1,%2,%3}, [%4];" \
        : "=r"((r)[0]), "=r"((r)[1]), "=r"((r)[2]), "=r"((r)[3]) : "r"(addr))
#define LDMX2(r, addr) \
    asm volatile("ldmatrix.sync.aligned.m8n8.x2.shared.b16 {%0,%1}, [%2];" \
        : "=r"((r)[0]), "=r"((r)[1]) : "r"(addr))
#define MMA(c, a, b) \
    asm volatile("mma.sync.aligned.m16n8k16.row.col.f32.bf16.bf16.f32 " \
        "{%0,%1,%2,%3}, {%4,%5,%6,%7}, {%8,%9}, {%0,%1,%2,%3};" \
        : "+f"((c)[0]), "+f"((c)[1]), "+f"((c)[2]), "+f"((c)[3]) \
        : "r"((a)[0]), "r"((a)[1]), "r"((a)[2]), "r"((a)[3]), "r"((b)[0]), "r"((b)[1]))

// ================= bf16x3 mma.sync GEMM =================
// C[bz][m][n] = sum_k A[m][k]*B[n][k]; A/B split hi+lo bf16, K-major rows.
// CTA tile 128x128x32, 8 warps (2x4), warp tile 64x32. Double-buffered cp.async.
// M,N multiples of 128; K multiple of 32.
#define GM_PAD 40                      // bf16 elems per smem row
#define GM_TILE_B (128 * GM_PAD * 2)   // 10240 bytes per tile
#define GM_STAGE_B (4 * GM_TILE_B)     // Ah,Al,Bh,Bl

__global__ void __launch_bounds__(256, 1) gemm_mma(
    const __nv_bfloat16* __restrict__ Ahi, const __nv_bfloat16* __restrict__ Alo,
    const __nv_bfloat16* __restrict__ Bhi, const __nv_bfloat16* __restrict__ Blo,
    float* __restrict__ C, int K, int ldc, long sA, long sB, long sC)
{
    extern __shared__ char smem[];
    uint32_t sb = smem_u32(smem);
    int tid = threadIdx.x, lane = tid & 31, warp = tid >> 5;
    int wm = warp >> 2, wn = warp & 3;                 // 2 x 4 warp grid
    int m0 = blockIdx.y * 128, n0 = blockIdx.x * 128;

    const __nv_bfloat16* ah  = Ahi + (size_t)blockIdx.z * sA + (size_t)m0 * K;
    const __nv_bfloat16* al  = Alo + (size_t)blockIdx.z * sA + (size_t)m0 * K;
    const __nv_bfloat16* bh  = Bhi + (size_t)blockIdx.z * sB + (size_t)n0 * K;
    const __nv_bfloat16* bl_ = Blo + (size_t)blockIdx.z * sB + (size_t)n0 * K;
    C += (size_t)blockIdx.z * sC;

    int nk = K >> 5;

    // ---- staging lambda: copy 4 tiles (128x32 bf16 each) for k-chunk kt into stage st
    auto stage = [&](int st, int kt) {
        int k0 = kt * 32;
        uint32_t base = sb + st * GM_STAGE_B;
        #pragma unroll
        for (int t = 0; t < 4; t++) {
            const __nv_bfloat16* src =
                (t == 0 ? ah : t == 1 ? al : t == 2 ? bh : bl_) + k0;
            uint32_t dst = base + t * GM_TILE_B;
            #pragma unroll
            for (int rep = 0; rep < 2; rep++) {
                int j = tid + rep * 256;
                int r = j >> 2, c = (j & 3) * 8;
                cp16(dst + (uint32_t)(r * GM_PAD + c) * 2, src + (size_t)r * K + c);
            }
        }
    };

    float acc[4][4][4] = {};

    stage(0, 0);
    CP_COMMIT();

    // ldmatrix address components (within a tile, byte offsets)
    int a_row = wm * 64 + (lane & 15);                 // + mi*16
    int a_koff = 8 * (lane >> 4);                      // k-half select
    int b_row = wn * 32 + (lane & 7);                  // + ni*8
    int b_koff = 8 * ((lane >> 3) & 1);

    for (int kt = 0; kt < nk; kt++) {
        if (kt + 1 < nk) { stage((kt + 1) & 1, kt + 1); CP_COMMIT(); CP_WAIT(1); }
        else             { CP_WAIT(0); }
        __syncthreads();

        uint32_t tb = sb + (kt & 1) * GM_STAGE_B;
        #pragma unroll
        for (int ks = 0; ks < 2; ks++) {
            int kb = ks * 16;
            uint32_t afh[4][4], afl[4][4], bfh[4][2], bfl[4][2];
            #pragma unroll
            for (int mi = 0; mi < 4; mi++) {
                uint32_t ad = tb + (uint32_t)((a_row + mi * 16) * GM_PAD + kb + a_koff) * 2;
                LDMX4(afh[mi], ad);
                LDMX4(afl[mi], ad + GM_TILE_B);
            }
            #pragma unroll
            for (int ni = 0; ni < 4; ni++) {
                uint32_t bd = tb + 2 * GM_TILE_B
                            + (uint32_t)((b_row + ni * 8) * GM_PAD + kb + b_koff) * 2;
                LDMX2(bfh[ni], bd);
                LDMX2(bfl[ni], bd + GM_TILE_B);
            }
            #pragma unroll
            for (int mi = 0; mi < 4; mi++)
                #pragma unroll
                for (int ni = 0; ni < 4; ni++) {
                    MMA(acc[mi][ni], afh[mi], bfh[ni]);
                    MMA(acc[mi][ni], afh[mi], bfl[ni]);
                    MMA(acc[mi][ni], afl[mi], bfh[ni]);
                }
        }
        __syncthreads();
    }

    // ---- epilogue: fragment layout c0/c1 row gid, c2/c3 row gid+8, cols 2t,2t+1
    int gid = lane >> 2, tig = lane & 3;
    #pragma unroll
    for (int mi = 0; mi < 4; mi++) {
        int row = m0 + wm * 64 + mi * 16 + gid;
        #pragma unroll
        for (int ni = 0; ni < 4; ni++) {
            int col = n0 + wn * 32 + ni * 8 + tig * 2;
            *(float2*)(C + (size_t)row * ldc + col)       = make_float2(acc[mi][ni][0], acc[mi][ni][1]);
            *(float2*)(C + (size_t)(row + 8) * ldc + col) = make_float2(acc[mi][ni][2], acc[mi][ni][3]);
        }
    }
}

// ================= fp32 -> bf16 hi/lo split =================
__global__ void split_kernel(const float* __restrict__ s, __nv_bfloat16* __restrict__ hi,
                             __nv_bfloat16* __restrict__ lo, int n)
{
    int i = blockIdx.x * 256 + threadIdx.x;
    if (i < n) {
        float v = s[i];
        __nv_bfloat16 h = __float2bfloat16(v);
        hi[i] = h;
        lo[i] = __float2bfloat16(v - __bfloat162float(h));
    }
}

// ================= depthwise conv + SiLU (both branches, z = b + 2*rev) =================
__global__ void conv_silu_kernel(const float* __restrict__ xz,
                                 const float* __restrict__ w0, const float* __restrict__ b0,
                                 const float* __restrict__ w1, const float* __restrict__ b1,
                                 float* __restrict__ out0, float* __restrict__ out1)
{
    int z = blockIdx.z;
    int b = z & 1, rev = z >> 1;
    const float* w    = rev ? w1 : w0;
    const float* bias = rev ? b1 : b0;
    float* out        = rev ? out1 : out0;
    int t = blockIdx.x * blockDim.x + threadIdx.x;
    int d = blockIdx.y;
    const float* xp = xz + ((size_t)b * E2 + d) * L_SEQ;
    float acc = bias[d];
    #pragma unroll
    for (int k = 0; k < 4; k++) {
        int s = t - 3 + k;
        float xv = 0.f;
        if (s >= 0) xv = xp[rev ? (L_SEQ - 1 - s) : s];
        acc = fmaf(w[d * 4 + k], xv, acc);
    }
    out[((size_t)b * D_INNER + d) * L_SEQ + t] = acc / (1.f + __expf(-acc));
}

// ================= x_dbl GEMM (SIMT, both branches, z = b + 2*br) =================
__global__ void gemm_xdbl(const float* __restrict__ Wx0, const float* __restrict__ Wx1,
                          const float* __restrict__ xc0, const float* __restrict__ xc1,
                          float* __restrict__ xd0, float* __restrict__ xd1)
{
    int z = blockIdx.z, b = z & 1, br = z >> 1;
    const float* A  = br ? Wx1 : Wx0;
    const float* Bm = (br ? xc1 : xc0) + (size_t)b * D_INNER * L_SEQ;
    float* C        = (br ? xd1 : xd0) + (size_t)b * KDBL * L_SEQ;
    const int M = KDBL, K = D_INNER, lda = D_INNER, ldb = L_SEQ, ldc = L_SEQ;

    __shared__ float As[16][68];
    __shared__ float Bs[16][64];
    int tid = threadIdx.x;
    int tx = tid & 15, ty = tid >> 4;
    int row0 = blockIdx.y * 64, col0 = blockIdx.x * 64;
    float acc[4][4] = {};
    for (int k0 = 0; k0 < K; k0 += 16) {
        {
            int m = tid >> 2, k4 = (tid & 3) * 4;
            float4 v = make_float4(0.f, 0.f, 0.f, 0.f);
            if (row0 + m < M) v = *(const float4*)(A + (size_t)(row0 + m) * lda + k0 + k4);
            As[k4 + 0][m] = v.x; As[k4 + 1][m] = v.y; As[k4 + 2][m] = v.z; As[k4 + 3][m] = v.w;
        }
        {
            int k = tid >> 4, n4 = (tid & 15) * 4;
            *(float4*)&Bs[k][n4] = *(const float4*)(Bm + (size_t)(k0 + k) * ldb + col0 + n4);
        }
        __syncthreads();
        #pragma unroll
        for (int k = 0; k < 16; k++) {
            float4 av = *(const float4*)&As[k][ty * 4];
            float4 bv = *(const float4*)&Bs[k][tx * 4];
            float aa[4] = {av.x, av.y, av.z, av.w}, bb[4] = {bv.x, bv.y, bv.z, bv.w};
            #pragma unroll
            for (int i = 0; i < 4; i++)
                #pragma unroll
                for (int j = 0; j < 4; j++) acc[i][j] = fmaf(aa[i], bb[j], acc[i][j]);
        }
        __syncthreads();
    }
    #pragma unroll
    for (int i = 0; i < 4; i++) {
        int r = row0 + ty * 4 + i;
        if (r < M)
            *(float4*)(C + (size_t)r * ldc + col0 + tx * 4) =
                make_float4(acc[i][0], acc[i][1], acc[i][2], acc[i][3]);
    }
}

// ================= dt: register-resident dt_lo, smem-broadcast W_dt =================
#define DT_DC 96
__global__ void __launch_bounds__(256) dt_kernel2(
    const float* __restrict__ xd0, const float* __restrict__ xd1,
    const float* __restrict__ Wdt, const float* __restrict__ Wdtb,
    const float* __restrict__ bdt, const float* __restrict__ bdtb,
    float* __restrict__ dt0, float* __restrict__ dt1)
{
    __shared__ float sw_[DT_DC][DT_RANK];
    int z = blockIdx.z, b = z & 1, br = z >> 1;
    const float* xd = (br ? xd1 : xd0) + (size_t)b * KDBL * L_SEQ;
    const float* W  = br ? Wdtb : Wdt;
    const float* bb = br ? bdtb : bdt;
    float* out = (br ? dt1 : dt0) + (size_t)b * D_INNER * L_SEQ;
    int tid = threadIdx.x;
    int t  = blockIdx.x * 256 + tid;
    int d0 = blockIdx.y * DT_DC;

    float xr[DT_RANK];
    #pragma unroll
    for (int r = 0; r < DT_RANK; r++) xr[r] = xd[(size_t)r * L_SEQ + t];
    for (int i = tid; i < DT_DC * DT_RANK; i += 256) sw_[i / DT_RANK][i % DT_RANK] = W[d0 * DT_RANK + i];
    __syncthreads();

    for (int dd = 0; dd < DT_DC; dd++) {
        float acc = __ldg(bb + d0 + dd);
        #pragma unroll
        for (int r = 0; r < DT_RANK; r++) acc = fmaf(sw_[dd][r], xr[r], acc);
        float sp = (acc > 20.f) ? acc : log1pf(__expf(acc));
        out[(size_t)(d0 + dd) * L_SEQ + t] = sp;
    }
}

// ================= B/C transpose (both branches) =================
__global__ void bc_kernel(const float* __restrict__ xd0, const float* __restrict__ xd1,
                          float* __restrict__ bc0, float* __restrict__ bc1)
{
    int idx = blockIdx.x * 256 + threadIdx.x;     // 2 * B_SZ*L_SEQ*32 = 262144
    int br = idx >> 17;
    int j  = idx & 131071;
    int i  = j & 31, t = (j >> 5) & (L_SEQ - 1), b = j >> 16;
    const float* xd = br ? xd1 : xd0;
    float* bc       = br ? bc1 : bc0;
    bc[j] = xd[(size_t)b * KDBL * L_SEQ + (size_t)(DT_RANK + i) * L_SEQ + t];
}

// ================= selective scan (both branches) =================
__global__ void scan_kernel(const float* __restrict__ xc0, const float* __restrict__ xc1,
                            const float* __restrict__ dt0, const float* __restrict__ dt1,
                            const float* __restrict__ bc0, const float* __restrict__ bc1,
                            const float* __restrict__ Af, const float* __restrict__ Ab,
                            const float* __restrict__ Df, const float* __restrict__ Db,
                            float* __restrict__ y0, float* __restrict__ y1)
{
    int br = blockIdx.y;
    const float* xc = br ? xc1 : xc0;
    const float* dt = br ? dt1 : dt0;
    const float* bc = br ? bc1 : bc0;
    const float* Alog = br ? Ab : Af;
    const float* Dp   = br ? Db : Df;
    float* y = br ? y1 : y0;

    int half = threadIdx.x >> 4;
    int n    = threadIdx.x & 15;
    int row  = blockIdx.x * 16 + half;
    int b = row / D_INNER, d = row % D_INNER;

    float a  = -__expf(Alog[d * D_STATE + n]);
    float Dv = Dp[d];
    const float* dtp = dt + (size_t)row * L_SEQ;
    const float* xp  = xc + (size_t)row * L_SEQ;
    const float* bcp = bc + (size_t)b * L_SEQ * 32;
    float* yp = y + (size_t)row * L_SEQ;

    float h = 0.f;
    #pragma unroll 2
    for (int t = 0; t < L_SEQ; t++) {
        float dtv = __ldg(dtp + t);
        float xv  = __ldg(xp + t);
        float bv  = __ldg(bcp + t * 32 + n);
        float cv  = __ldg(bcp + t * 32 + 16 + n);
        float dA  = __expf(dtv * a);
        h = fmaf(dA, h, dtv * xv * bv);
        float p = h * cv;
        p += __shfl_xor_sync(0xffffffffu, p, 1);
        p += __shfl_xor_sync(0xffffffffu, p, 2);
        p += __shfl_xor_sync(0xffffffffu, p, 4);
        p += __shfl_xor_sync(0xffffffffu, p, 8);
        if (n == 0) yp[t] = fmaf(Dv, xv, p);
    }
}

// ================= combine + transpose -> bf16 hi/lo [b][t][d] =================
__global__ void combine_t(const float* __restrict__ xz, const float* __restrict__ yf,
                          const float* __restrict__ yb,
                          __nv_bfloat16* __restrict__ chi, __nv_bfloat16* __restrict__ clo)
{
    __shared__ float s[32][33];
    int b = blockIdx.z;
    int t0 = blockIdx.x * 32, d0 = blockIdx.y * 32;
    int tid = threadIdx.x;
    int tl = tid & 31, dg = tid >> 5;
    #pragma unroll
    for (int i = 0; i < 4; i++) {
        int d = d0 + dg + i * 8;
        int t = t0 + tl;
        size_t bd = (size_t)b * D_INNER + d;
        float z  = xz[((size_t)b * E2 + D_INNER + d) * L_SEQ + t];
        float sz = z / (1.f + __expf(-z));
        float v  = 0.5f * sz * (yf[bd * L_SEQ + t] + yb[bd * L_SEQ + (L_SEQ - 1 - t)]);
        s[dg + i * 8][tl] = v;
    }
    __syncthreads();
    #pragma unroll
    for (int i = 0; i < 4; i++) {
        int t = t0 + dg + i * 8;
        int d = d0 + tl;
        float v = s[tl][dg + i * 8];
        __nv_bfloat16 h = __float2bfloat16(v);
        size_t o = ((size_t)b * L_SEQ + t) * D_INNER + d;
        chi[o] = h;
        clo[o] = __float2bfloat16(v - __bfloat162float(h));
    }
}

// ================= host launcher =================
extern "C" void kernel_launch(void* const* d_in, const int* in_sizes, int n_in,
                              void* d_out, int out_size)
{
    (void)in_sizes; (void)n_in; (void)out_size;
    const float* hidden   = (const float*)d_in[0];
    const float* W_in     = (const float*)d_in[1];
    const float* conv_w   = (const float*)d_in[2];
    const float* conv_b   = (const float*)d_in[3];
    const float* conv_w_b = (const float*)d_in[4];
    const float* conv_b_b = (const float*)d_in[5];
    const float* W_x      = (const float*)d_in[6];
    const float* W_x_b    = (const float*)d_in[7];
    const float* W_dt     = (const float*)d_in[8];
    const float* b_dt     = (const float*)d_in[9];
    const float* W_dt_b   = (const float*)d_in[10];
    const float* b_dt_b   = (const float*)d_in[11];
    const float* A_log    = (const float*)d_in[12];
    const float* A_b_log  = (const float*)d_in[13];
    const float* Dp       = (const float*)d_in[14];
    const float* Dp_b     = (const float*)d_in[15];
    const float* W_out    = (const float*)d_in[16];

    float *xz, *xcb, *xdb, *dtb, *bcb, *yb_;
    __nv_bfloat16 *winh, *winl, *hidh, *hidl, *wouth, *woutl, *chi, *clo;
    cudaGetSymbolAddress((void**)&xz,   g_xz);
    cudaGetSymbolAddress((void**)&xcb,  g_xc);
    cudaGetSymbolAddress((void**)&xdb,  g_xdbl);
    cudaGetSymbolAddress((void**)&dtb,  g_dt);
    cudaGetSymbolAddress((void**)&bcb,  g_bc);
    cudaGetSymbolAddress((void**)&yb_,  g_y);
    cudaGetSymbolAddress((void**)&winh, g_winh);  cudaGetSymbolAddress((void**)&winl, g_winl);
    cudaGetSymbolAddress((void**)&hidh, g_hidh);  cudaGetSymbolAddress((void**)&hidl, g_hidl);
    cudaGetSymbolAddress((void**)&wouth, g_wouth); cudaGetSymbolAddress((void**)&woutl, g_woutl);
    cudaGetSymbolAddress((void**)&chi,  g_chi);   cudaGetSymbolAddress((void**)&clo,  g_clo);

    const size_t S_XC = (size_t)B_SZ * D_INNER * L_SEQ;
    const size_t S_XD = (size_t)B_SZ * KDBL * L_SEQ;
    const size_t S_BC = (size_t)B_SZ * L_SEQ * 32;
    float* xc0 = xcb;  float* xc1 = xcb + S_XC;
    float* xd0 = xdb;  float* xd1 = xdb + S_XD;
    float* dt0 = dtb;  float* dt1 = dtb + S_XC;
    float* bc0 = bcb;  float* bc1 = bcb + S_BC;
    float* y0  = yb_;  float* y1  = yb_ + S_XC;

    const int SMEM_MMA = 2 * GM_STAGE_B;  // 81920
    cudaFuncSetAttribute(gemm_mma, cudaFuncAttributeMaxDynamicSharedMemorySize, SMEM_MMA);

    dim3 blk(256);

    // 0) fp32 -> bf16 hi/lo splits
    split_kernel<<<(E2 * D_MODEL + 255) / 256, blk>>>(W_in, winh, winl, E2 * D_MODEL);
    split_kernel<<<(B_SZ * L_SEQ * D_MODEL + 255) / 256, blk>>>(hidden, hidh, hidl, B_SZ * L_SEQ * D_MODEL);
    split_kernel<<<(D_MODEL * D_INNER + 255) / 256, blk>>>(W_out, wouth, woutl, D_MODEL * D_INNER);

    // 1) xz[b][e][l] = W_in @ hidden^T  (mma.sync bf16x3)
    gemm_mma<<<dim3(L_SEQ / 128, E2 / 128, B_SZ), blk, SMEM_MMA>>>(
        winh, winl, hidh, hidl, xz, D_MODEL, L_SEQ,
        0L, (long)L_SEQ * D_MODEL, (long)E2 * L_SEQ);

    // 2) conv + silu, both branches
    conv_silu_kernel<<<dim3(L_SEQ / 256, D_INNER, 4), blk>>>(
        xz, conv_w, conv_b, conv_w_b, conv_b_b, xc0, xc1);

    // 3) x_dbl, both branches
    gemm_xdbl<<<dim3(L_SEQ / 64, 2, 4), blk>>>(W_x, W_x_b, xc0, xc1, xd0, xd1);

    // 4) dt, both branches
    dt_kernel2<<<dim3(L_SEQ / 256, D_INNER / DT_DC, 4), blk>>>(
        xd0, xd1, W_dt, W_dt_b, b_dt, b_dt_b, dt0, dt1);

    // 5) B/C transpose, both branches
    bc_kernel<<<(2 * B_SZ * L_SEQ * 32) / 256, blk>>>(xd0, xd1, bc0, bc1);

    // 6) selective scan, both branches
    scan_kernel<<<dim3(B_SZ * D_INNER / 16, 2), blk>>>(
        xc0, xc1, dt0, dt1, bc0, bc1, A_log, A_b_log, Dp, Dp_b, y0, y1);

    // 7) combine -> transposed bf16 hi/lo
    combine_t<<<dim3(L_SEQ / 32, D_INNER / 32, B_SZ), blk>>>(xz, y0, y1, chi, clo);

    // 8) out[b][l][m] = comb[b][l][:] @ W_out^T  (mma.sync bf16x3)
    gemm_mma<<<dim3(D_MODEL / 128, L_SEQ / 128, B_SZ), blk, SMEM_MMA>>>(
        chi, clo, wouth, woutl, (float*)d_out, D_INNER, D_MODEL,
        (long)L_SEQ * D_INNER, 0L, (long)L_SEQ * D_MODEL);
}

// round 10
// speedup vs baseline: 2.4736x; 1.2681x over previous
#include <cuda_runtime.h>
#include <cuda_bf16.h>
#include <math.h>
#include <stdint.h>

#define B_SZ    2
#define L_SEQ   2048
#define D_MODEL 768
#define D_INNER 1536
#define E2      3072
#define D_STATE 16
#define DT_RANK 48
#define KDBL    80
#define D_CONV  4

// ---------------- scratch (device globals) ----------------
__device__ float g_xz  [B_SZ * E2 * L_SEQ];
__device__ float g_xc  [2][B_SZ * D_INNER * L_SEQ];
__device__ float g_xdp [2 * B_SZ * 128 * L_SEQ];        // padded x_dbl: [br][b][128][L]
__device__ float g_dt  [2][B_SZ * D_INNER * L_SEQ];
__device__ float g_bc  [2][B_SZ * L_SEQ * 32];
__device__ float g_y   [2][B_SZ * D_INNER * L_SEQ];

// bf16 hi/lo split buffers
__device__ __nv_bfloat16 g_winh[E2 * D_MODEL],      g_winl[E2 * D_MODEL];
__device__ __nv_bfloat16 g_hidh[B_SZ * L_SEQ * D_MODEL], g_hidl[B_SZ * L_SEQ * D_MODEL];
__device__ __nv_bfloat16 g_wouth[D_MODEL * D_INNER], g_woutl[D_MODEL * D_INNER];
__device__ __nv_bfloat16 g_chi[B_SZ * L_SEQ * D_INNER], g_clo[B_SZ * L_SEQ * D_INNER];
__device__ __nv_bfloat16 g_xth[2 * B_SZ * L_SEQ * D_INNER], g_xtl[2 * B_SZ * L_SEQ * D_INNER]; // xc^T [br][b][t][d]
__device__ __nv_bfloat16 g_wxph[2 * 128 * D_INNER], g_wxpl[2 * 128 * D_INNER];                 // padded W_x

// ================= helpers (base-target sm_103 safe) =================
__device__ __forceinline__ uint32_t smem_u32(const void* p) {
    uint32_t a;
    asm("{ .reg .u64 t; cvta.to.shared.u64 t, %1; cvt.u32.u64 %0, t; }" : "=r"(a) : "l"(p));
    return a;
}
__device__ __forceinline__ void cp16(uint32_t s, const void* g) {
    asm volatile("cp.async.cg.shared.global [%0], [%1], 16;" :: "r"(s), "l"(g));
}
#define CP_COMMIT() asm volatile("cp.async.commit_group;" ::: "memory")
#define CP_WAIT(N)  asm volatile("cp.async.wait_group %0;" :: "n"(N) : "memory")

#define LDMX4(r, addr) \
    asm volatile("ldmatrix.sync.aligned.m8n8.x4.shared.b16 {%0,%1,%2,%3}, [%4];" \
        : "=r"((r)[0]), "=r"((r)[1]), "=r"((r)[2]), "=r"((r)[3]) : "r"(addr))
#define LDMX2(r, addr) \
    asm volatile("ldmatrix.sync.aligned.m8n8.x2.shared.b16 {%0,%1}, [%2];" \
        : "=r"((r)[0]), "=r"((r)[1]) : "r"(addr))
#define MMA(c, a, b) \
    asm volatile("mma.sync.aligned.m16n8k16.row.col.f32.bf16.bf16.f32 " \
        "{%0,%1,%2,%3}, {%4,%5,%6,%7}, {%8,%9}, {%0,%1,%2,%3};" \
        : "+f"((c)[0]), "+f"((c)[1]), "+f"((c)[2]), "+f"((c)[3]) \
        : "r"((a)[0]), "r"((a)[1]), "r"((a)[2]), "r"((a)[3]), "r"((b)[0]), "r"((b)[1]))

// ================= bf16x3 mma.sync GEMM, 4-stage pipeline =================
// z decodes: b = z&1, br = z>>1. C[m][n] = sum_k A[m][k]*B[n][k], K-major rows.
// CTA tile 128 x TN x 32; 8 warps (2 x 4); warp tile 64 x TN/4.
#define GM_PAD 40

template<int TN>
__global__ void __launch_bounds__(256, 1) gemm_mma(
    const __nv_bfloat16* __restrict__ Ahi, const __nv_bfloat16* __restrict__ Alo,
    const __nv_bfloat16* __restrict__ Bhi, const __nv_bfloat16* __restrict__ Blo,
    float* __restrict__ C, int K, int ldc,
    long sAb, long sAr, long sBb, long sBr, long sCb, long sCr)
{
    constexpr int TM = 128;
    constexpr int AT = TM * GM_PAD * 2;      // bytes per A sub-tile
    constexpr int BT = TN * GM_PAD * 2;
    constexpr int STG = 2 * AT + 2 * BT;
    constexpr int WN = TN / 4;               // warp n-extent
    constexpr int NI = WN / 8;
    extern __shared__ char smem[];
    uint32_t sb = smem_u32(smem);
    int tid = threadIdx.x, lane = tid & 31, warp = tid >> 5;
    int wm = warp >> 2, wn = warp & 3;
    int m0 = blockIdx.y * TM, n0 = blockIdx.x * TN;
    long zb = blockIdx.z & 1, zr = blockIdx.z >> 1;

    const __nv_bfloat16* ah  = Ahi + zb * sAb + zr * sAr + (size_t)m0 * K;
    const __nv_bfloat16* al  = Alo + zb * sAb + zr * sAr + (size_t)m0 * K;
    const __nv_bfloat16* bh  = Bhi + zb * sBb + zr * sBr + (size_t)n0 * K;
    const __nv_bfloat16* bl_ = Blo + zb * sBb + zr * sBr + (size_t)n0 * K;
    C += zb * sCb + zr * sCr;

    int nk = K >> 5;

    auto stage = [&](int slot, int kt) {
        int k0 = kt << 5;
        uint32_t base = sb + slot * STG;
        #pragma unroll
        for (int j = tid; j < TM * 4; j += 256) {
            int r = j >> 2, c = (j & 3) * 8;
            uint32_t off = (uint32_t)(r * GM_PAD + c) * 2;
            cp16(base + off,      ah + (size_t)r * K + k0 + c);
            cp16(base + AT + off, al + (size_t)r * K + k0 + c);
        }
        #pragma unroll
        for (int j = tid; j < TN * 4; j += 256) {
            int r = j >> 2, c = (j & 3) * 8;
            uint32_t off = (uint32_t)(r * GM_PAD + c) * 2;
            cp16(base + 2 * AT + off,      bh  + (size_t)r * K + k0 + c);
            cp16(base + 2 * AT + BT + off, bl_ + (size_t)r * K + k0 + c);
        }
    };

    float acc[4][NI][4] = {};

    stage(0, 0); CP_COMMIT();
    stage(1, 1); CP_COMMIT();
    stage(2, 2); CP_COMMIT();

    int a_row  = wm * 64 + (lane & 15);
    int a_koff = 8 * (lane >> 4);
    int b_row  = wn * WN + (lane & 7);
    int b_koff = 8 * ((lane >> 3) & 1);

    for (int kt = 0; kt < nk; kt++) {
        int pend = nk - kt;
        if (pend >= 3)      CP_WAIT(2);
        else if (pend == 2) CP_WAIT(1);
        else                CP_WAIT(0);
        __syncthreads();

        uint32_t tb = sb + (kt & 3) * STG;
        #pragma unroll
        for (int ks = 0; ks < 2; ks++) {
            int kb = ks * 16;
            uint32_t afh[4][4], afl[4][4], bfh[NI][2], bfl[NI][2];
            #pragma unroll
            for (int mi = 0; mi < 4; mi++) {
                uint32_t ad = tb + (uint32_t)((a_row + mi * 16) * GM_PAD + kb + a_koff) * 2;
                LDMX4(afh[mi], ad);
                LDMX4(afl[mi], ad + AT);
            }
            #pragma unroll
            for (int ni = 0; ni < NI; ni++) {
                uint32_t bd = tb + 2 * AT + (uint32_t)((b_row + ni * 8) * GM_PAD + kb + b_koff) * 2;
                LDMX2(bfh[ni], bd);
                LDMX2(bfl[ni], bd + BT);
            }
            // term-major ordering: no back-to-back same-accumulator MMAs
            #pragma unroll
            for (int mi = 0; mi < 4; mi++)
                #pragma unroll
                for (int ni = 0; ni < NI; ni++) MMA(acc[mi][ni], afh[mi], bfh[ni]);
            #pragma unroll
            for (int mi = 0; mi < 4; mi++)
                #pragma unroll
                for (int ni = 0; ni < NI; ni++) MMA(acc[mi][ni], afh[mi], bfl[ni]);
            #pragma unroll
            for (int mi = 0; mi < 4; mi++)
                #pragma unroll
                for (int ni = 0; ni < NI; ni++) MMA(acc[mi][ni], afl[mi], bfh[ni]);
        }
        if (kt + 3 < nk) { stage((kt + 3) & 3, kt + 3); CP_COMMIT(); }
    }

    int gid = lane >> 2, tig = lane & 3;
    #pragma unroll
    for (int mi = 0; mi < 4; mi++) {
        int row = m0 + wm * 64 + mi * 16 + gid;
        #pragma unroll
        for (int ni = 0; ni < NI; ni++) {
            int col = n0 + wn * WN + ni * 8 + tig * 2;
            *(float2*)(C + (size_t)row * ldc + col)       = make_float2(acc[mi][ni][0], acc[mi][ni][1]);
            *(float2*)(C + (size_t)(row + 8) * ldc + col) = make_float2(acc[mi][ni][2], acc[mi][ni][3]);
        }
    }
}

// ================= fp32 -> bf16 hi/lo split =================
__global__ void split_kernel(const float* __restrict__ s, __nv_bfloat16* __restrict__ hi,
                             __nv_bfloat16* __restrict__ lo, int n)
{
    int i = blockIdx.x * 256 + threadIdx.x;
    if (i < n) {
        float v = s[i];
        __nv_bfloat16 h = __float2bfloat16(v);
        hi[i] = h;
        lo[i] = __float2bfloat16(v - __bfloat162float(h));
    }
}

// ================= padded W_x -> bf16 hi/lo [2][128][D_INNER] =================
__global__ void padwx_kernel(const float* __restrict__ Wx, const float* __restrict__ Wxb,
                             __nv_bfloat16* __restrict__ h, __nv_bfloat16* __restrict__ l)
{
    int idx = blockIdx.x * 256 + threadIdx.x;     // 2*128*1536
    if (idx >= 2 * 128 * D_INNER) return;
    int br = idx / (128 * D_INNER);
    int j  = idx % (128 * D_INNER);
    int r  = j / D_INNER;
    float v = 0.f;
    if (r < KDBL) v = (br ? Wxb : Wx)[j];
    __nv_bfloat16 hh = __float2bfloat16(v);
    h[idx] = hh;
    l[idx] = __float2bfloat16(v - __bfloat162float(hh));
}

// ================= conv + SiLU, tiled: writes xc[d][t] fp32 AND xc^T[t][d] bf16 hi/lo =================
__global__ void conv_silu_t(const float* __restrict__ xz,
                            const float* __restrict__ w0, const float* __restrict__ b0,
                            const float* __restrict__ w1, const float* __restrict__ b1,
                            float* __restrict__ xc0, float* __restrict__ xc1,
                            __nv_bfloat16* __restrict__ xth, __nv_bfloat16* __restrict__ xtl)
{
    __shared__ float s[32][33];
    int z = blockIdx.z, b = z & 1, rev = z >> 1;
    const float* w    = rev ? w1 : w0;
    const float* bias = rev ? b1 : b0;
    float* xc = (rev ? xc1 : xc0) + (size_t)b * D_INNER * L_SEQ;
    __nv_bfloat16* th = xth + ((size_t)(rev * B_SZ + b) * L_SEQ) * D_INNER;
    __nv_bfloat16* tl = xtl + ((size_t)(rev * B_SZ + b) * L_SEQ) * D_INNER;
    int t0 = blockIdx.x * 32, d0 = blockIdx.y * 32;
    int tid = threadIdx.x;
    int tt = tid & 31, dg = tid >> 5;

    #pragma unroll
    for (int i = 0; i < 4; i++) {
        int d = d0 + dg + i * 8;
        int t = t0 + tt;
        const float* xp = xz + ((size_t)b * E2 + d) * L_SEQ;
        float acc = bias[d];
        #pragma unroll
        for (int k = 0; k < 4; k++) {
            int ss = t - 3 + k;
            float xv = 0.f;
            if (ss >= 0) xv = xp[rev ? (L_SEQ - 1 - ss) : ss];
            acc = fmaf(w[d * 4 + k], xv, acc);
        }
        float v = acc / (1.f + __expf(-acc));
        xc[(size_t)d * L_SEQ + t] = v;
        s[dg + i * 8][tt] = v;
    }
    __syncthreads();
    #pragma unroll
    for (int i = 0; i < 4; i++) {
        int t = t0 + dg + i * 8;
        int d = d0 + tt;
        float v = s[tt][dg + i * 8];
        __nv_bfloat16 h = __float2bfloat16(v);
        size_t o = (size_t)t * D_INNER + d;
        th[o] = h;
        tl[o] = __float2bfloat16(v - __bfloat162float(h));
    }
}

// ================= dt: register-resident dt_lo, smem-broadcast W_dt =================
#define DT_DC 96
__global__ void __launch_bounds__(256) dt_kernel2(
    const float* __restrict__ xdp,
    const float* __restrict__ Wdt, const float* __restrict__ Wdtb,
    const float* __restrict__ bdt, const float* __restrict__ bdtb,
    float* __restrict__ dt0, float* __restrict__ dt1)
{
    __shared__ float sw_[DT_DC][DT_RANK];
    int z = blockIdx.z, b = z & 1, br = z >> 1;
    const float* xd = xdp + (size_t)(br * B_SZ + b) * 128 * L_SEQ;
    const float* W  = br ? Wdtb : Wdt;
    const float* bb = br ? bdtb : bdt;
    float* out = (br ? dt1 : dt0) + (size_t)b * D_INNER * L_SEQ;
    int tid = threadIdx.x;
    int t  = blockIdx.x * 256 + tid;
    int d0 = blockIdx.y * DT_DC;

    float xr[DT_RANK];
    #pragma unroll
    for (int r = 0; r < DT_RANK; r++) xr[r] = xd[(size_t)r * L_SEQ + t];
    for (int i = tid; i < DT_DC * DT_RANK; i += 256) sw_[i / DT_RANK][i % DT_RANK] = W[d0 * DT_RANK + i];
    __syncthreads();

    for (int dd = 0; dd < DT_DC; dd++) {
        float acc = __ldg(bb + d0 + dd);
        #pragma unroll
        for (int r = 0; r < DT_RANK; r++) acc = fmaf(sw_[dd][r], xr[r], acc);
        float sp = (acc > 20.f) ? acc : log1pf(__expf(acc));
        out[(size_t)(d0 + dd) * L_SEQ + t] = sp;
    }
}

// ================= B/C transpose (both branches) =================
__global__ void bc_kernel(const float* __restrict__ xdp,
                          float* __restrict__ bc0, float* __restrict__ bc1)
{
    int idx = blockIdx.x * 256 + threadIdx.x;     // 2 * B_SZ*L_SEQ*32
    int br = idx >> 17;
    int j  = idx & 131071;
    int i  = j & 31, t = (j >> 5) & (L_SEQ - 1), b = j >> 16;
    float* bc = br ? bc1 : bc0;
    bc[j] = xdp[((size_t)(br * B_SZ + b) * 128 + DT_RANK + i) * L_SEQ + t];
}

// ================= selective scan (both branches), 4-wide unrolled =================
__global__ void scan_kernel(const float* __restrict__ xc0, const float* __restrict__ xc1,
                            const float* __restrict__ dt0, const float* __restrict__ dt1,
                            const float* __restrict__ bc0, const float* __restrict__ bc1,
                            const float* __restrict__ Af, const float* __restrict__ Ab,
                            const float* __restrict__ Df, const float* __restrict__ Db,
                            float* __restrict__ y0, float* __restrict__ y1)
{
    int br = blockIdx.y;
    const float* xc = br ? xc1 : xc0;
    const float* dt = br ? dt1 : dt0;
    const float* bc = br ? bc1 : bc0;
    const float* Alog = br ? Ab : Af;
    const float* Dp   = br ? Db : Df;
    float* y = br ? y1 : y0;

    int half = threadIdx.x >> 4;
    int n    = threadIdx.x & 15;
    int row  = blockIdx.x * 16 + half;
    int b = row / D_INNER, d = row % D_INNER;

    float a  = -__expf(Alog[d * D_STATE + n]);
    float Dv = Dp[d];
    const float* dtp = dt + (size_t)row * L_SEQ;
    const float* xp  = xc + (size_t)row * L_SEQ;
    const float* bcp = bc + (size_t)b * L_SEQ * 32;
    float* yp = y + (size_t)row * L_SEQ;

    float h = 0.f;
    for (int t = 0; t < L_SEQ; t += 4) {
        float4 dt4 = *(const float4*)(dtp + t);
        float4 x4  = *(const float4*)(xp + t);
        float dts[4] = {dt4.x, dt4.y, dt4.z, dt4.w};
        float xs[4]  = {x4.x,  x4.y,  x4.z,  x4.w};
        #pragma unroll
        for (int j = 0; j < 4; j++) {
            float bv = __ldg(bcp + (t + j) * 32 + n);
            float cv = __ldg(bcp + (t + j) * 32 + 16 + n);
            float dA = __expf(dts[j] * a);
            h = fmaf(dA, h, dts[j] * xs[j] * bv);
            float p = h * cv;
            p += __shfl_xor_sync(0xffffffffu, p, 1);
            p += __shfl_xor_sync(0xffffffffu, p, 2);
            p += __shfl_xor_sync(0xffffffffu, p, 4);
            p += __shfl_xor_sync(0xffffffffu, p, 8);
            if (n == 0) yp[t + j] = fmaf(Dv, xs[j], p);
        }
    }
}

// ================= combine + transpose -> bf16 hi/lo [b][t][d] =================
__global__ void combine_t(const float* __restrict__ xz, const float* __restrict__ yf,
                          const float* __restrict__ yb,
                          __nv_bfloat16* __restrict__ chi, __nv_bfloat16* __restrict__ clo)
{
    __shared__ float s[32][33];
    int b = blockIdx.z;
    int t0 = blockIdx.x * 32, d0 = blockIdx.y * 32;
    int tid = threadIdx.x;
    int tl = tid & 31, dg = tid >> 5;
    #pragma unroll
    for (int i = 0; i < 4; i++) {
        int d = d0 + dg + i * 8;
        int t = t0 + tl;
        size_t bd = (size_t)b * D_INNER + d;
        float z  = xz[((size_t)b * E2 + D_INNER + d) * L_SEQ + t];
        float sz = z / (1.f + __expf(-z));
        float v  = 0.5f * sz * (yf[bd * L_SEQ + t] + yb[bd * L_SEQ + (L_SEQ - 1 - t)]);
        s[dg + i * 8][tl] = v;
    }
    __syncthreads();
    #pragma unroll
    for (int i = 0; i < 4; i++) {
        int t = t0 + dg + i * 8;
        int d = d0 + tl;
        float v = s[tl][dg + i * 8];
        __nv_bfloat16 h = __float2bfloat16(v);
        size_t o = ((size_t)b * L_SEQ + t) * D_INNER + d;
        chi[o] = h;
        clo[o] = __float2bfloat16(v - __bfloat162float(h));
    }
}

// ================= host launcher =================
extern "C" void kernel_launch(void* const* d_in, const int* in_sizes, int n_in,
                              void* d_out, int out_size)
{
    (void)in_sizes; (void)n_in; (void)out_size;
    const float* hidden   = (const float*)d_in[0];
    const float* W_in     = (const float*)d_in[1];
    const float* conv_w   = (const float*)d_in[2];
    const float* conv_b   = (const float*)d_in[3];
    const float* conv_w_b = (const float*)d_in[4];
    const float* conv_b_b = (const float*)d_in[5];
    const float* W_x      = (const float*)d_in[6];
    const float* W_x_b    = (const float*)d_in[7];
    const float* W_dt     = (const float*)d_in[8];
    const float* b_dt     = (const float*)d_in[9];
    const float* W_dt_b   = (const float*)d_in[10];
    const float* b_dt_b   = (const float*)d_in[11];
    const float* A_log    = (const float*)d_in[12];
    const float* A_b_log  = (const float*)d_in[13];
    const float* Dp       = (const float*)d_in[14];
    const float* Dp_b     = (const float*)d_in[15];
    const float* W_out    = (const float*)d_in[16];

    float *xz, *xcb, *xdp, *dtb, *bcb, *yb_;
    __nv_bfloat16 *winh, *winl, *hidh, *hidl, *wouth, *woutl, *chi, *clo, *xth, *xtl, *wxph, *wxpl;
    cudaGetSymbolAddress((void**)&xz,   g_xz);
    cudaGetSymbolAddress((void**)&xcb,  g_xc);
    cudaGetSymbolAddress((void**)&xdp,  g_xdp);
    cudaGetSymbolAddress((void**)&dtb,  g_dt);
    cudaGetSymbolAddress((void**)&bcb,  g_bc);
    cudaGetSymbolAddress((void**)&yb_,  g_y);
    cudaGetSymbolAddress((void**)&winh, g_winh);  cudaGetSymbolAddress((void**)&winl, g_winl);
    cudaGetSymbolAddress((void**)&hidh, g_hidh);  cudaGetSymbolAddress((void**)&hidl, g_hidl);
    cudaGetSymbolAddress((void**)&wouth, g_wouth); cudaGetSymbolAddress((void**)&woutl, g_woutl);
    cudaGetSymbolAddress((void**)&chi,  g_chi);   cudaGetSymbolAddress((void**)&clo,  g_clo);
    cudaGetSymbolAddress((void**)&xth,  g_xth);   cudaGetSymbolAddress((void**)&xtl,  g_xtl);
    cudaGetSymbolAddress((void**)&wxph, g_wxph);  cudaGetSymbolAddress((void**)&wxpl, g_wxpl);

    const size_t S_XC = (size_t)B_SZ * D_INNER * L_SEQ;
    const size_t S_BC = (size_t)B_SZ * L_SEQ * 32;
    float* xc0 = xcb;  float* xc1 = xcb + S_XC;
    float* dt0 = dtb;  float* dt1 = dtb + S_XC;
    float* bc0 = bcb;  float* bc1 = bcb + S_BC;
    float* y0  = yb_;  float* y1  = yb_ + S_XC;

    const int SMEM128 = 4 * (2 * 128 * GM_PAD * 2 + 2 * 128 * GM_PAD * 2);  // 163840
    const int SMEM64  = 4 * (2 * 128 * GM_PAD * 2 + 2 * 64  * GM_PAD * 2);  // 122880
    cudaFuncSetAttribute(gemm_mma<128>, cudaFuncAttributeMaxDynamicSharedMemorySize, SMEM128);
    cudaFuncSetAttribute(gemm_mma<64>,  cudaFuncAttributeMaxDynamicSharedMemorySize, SMEM64);

    dim3 blk(256);

    // 0) fp32 -> bf16 hi/lo splits + padded W_x
    split_kernel<<<(E2 * D_MODEL + 255) / 256, blk>>>(W_in, winh, winl, E2 * D_MODEL);
    split_kernel<<<(B_SZ * L_SEQ * D_MODEL + 255) / 256, blk>>>(hidden, hidh, hidl, B_SZ * L_SEQ * D_MODEL);
    split_kernel<<<(D_MODEL * D_INNER + 255) / 256, blk>>>(W_out, wouth, woutl, D_MODEL * D_INNER);
    padwx_kernel<<<(2 * 128 * D_INNER + 255) / 256, blk>>>(W_x, W_x_b, wxph, wxpl);

    // 1) xz = W_in @ hidden^T   (M=E2 rows, N=L cols, per b)
    gemm_mma<128><<<dim3(L_SEQ / 128, E2 / 128, B_SZ), blk, SMEM128>>>(
        winh, winl, hidh, hidl, xz, D_MODEL, L_SEQ,
        0L, 0L, (long)L_SEQ * D_MODEL, 0L, (long)E2 * L_SEQ, 0L);

    // 2) conv + silu (fp32 [d][t] + bf16 hi/lo transposed [t][d])
    conv_silu_t<<<dim3(L_SEQ / 32, D_INNER / 32, 4), blk>>>(
        xz, conv_w, conv_b, conv_w_b, conv_b_b, xc0, xc1, xth, xtl);

    // 3) x_dbl = W_x(padded) @ xc^T : M=128, N=L, K=D_INNER, z = b + 2*br
    gemm_mma<64><<<dim3(L_SEQ / 64, 1, 4), blk, SMEM64>>>(
        wxph, wxpl, xth, xtl, xdp, D_INNER, L_SEQ,
        0L, (long)128 * D_INNER,
        (long)L_SEQ * D_INNER, (long)B_SZ * L_SEQ * D_INNER,
        (long)128 * L_SEQ, (long)B_SZ * 128 * L_SEQ);

    // 4) dt, both branches
    dt_kernel2<<<dim3(L_SEQ / 256, D_INNER / DT_DC, 4), blk>>>(
        xdp, W_dt, W_dt_b, b_dt, b_dt_b, dt0, dt1);

    // 5) B/C transpose, both branches
    bc_kernel<<<(2 * B_SZ * L_SEQ * 32) / 256, blk>>>(xdp, bc0, bc1);

    // 6) selective scan, both branches
    scan_kernel<<<dim3(B_SZ * D_INNER / 16, 2), blk>>>(
        xc0, xc1, dt0, dt1, bc0, bc1, A_log, A_b_log, Dp, Dp_b, y0, y1);

    // 7) combine -> transposed bf16 hi/lo
    combine_t<<<dim3(L_SEQ / 32, D_INNER / 32, B_SZ), blk>>>(xz, y0, y1, chi, clo);

    // 8) out = comb @ W_out^T : M=L rows, N=D_MODEL
    gemm_mma<64><<<dim3(D_MODEL / 64, L_SEQ / 128, B_SZ), blk, SMEM64>>>(
        chi, clo, wouth, woutl, (float*)d_out, D_INNER, D_MODEL,
        (long)L_SEQ * D_INNER, 0L, 0L, 0L, (long)L_SEQ * D_MODEL, 0L);
}